// round 5
// baseline (speedup 1.0000x reference)
#include <cuda_runtime.h>
#include <cuda_bf16.h>

#define Bv   4
#define Nv   25200
#define MAXD 100
#define NBv  5
#define ARv  14
#define MRv  56
#define ATT  (NBv*ARv*ARv)     // 980
#define PIX  (MRv*MRv)         // 3136
#define V4PD (PIX/4)           // 784 float4 per detection
#define HALF (V4PD/2)          // 392 float4 per half
#define CPAD 8                 // channels padded 5 -> 8 in smem

#define OFF_BOX   4
#define OFF_SCR   (4 + Bv*MAXD*4)
#define OFF_CLS   (OFF_SCR + Bv*MAXD)
#define OFF_MSK   (OFF_CLS + Bv*MAXD)

__device__ __forceinline__ float ex2(float x) {
    float r; asm("ex2.approx.f32 %0, %1;" : "=f"(r) : "f"(x)); return r;
}
__device__ __forceinline__ float tanh_ap(float x) {
    float r; asm("tanh.approx.f32 %0, %1;" : "=f"(r) : "f"(x)); return r;
}

// smem layout: sa[(row*14 + col)*8 + ch], rows are an 8-row window (offset rowoff).
// Values pre-scaled by log2(e) so softmax uses bare ex2.
__device__ __forceinline__ float4 compute_item(int j, int rowoff,
                                               const float* __restrict__ sa,
                                               const float4* __restrict__ pv)
{
    const int y = j / (MRv/4);            // output row 0..55
    const int m = j - y * (MRv/4);        // float4 col group 0..13

    const float cy = y * 0.25f - 0.375f;
    const float fy = floorf(cy);
    const float wy = cy - fy;
    const int iy = (int)fy;
    const int r0 = max(0, min(ARv - 1, iy))     - rowoff;
    const int r1 = max(0, min(ARv - 1, iy + 1)) - rowoff;

    const int cm1 = max(m - 1, 0);
    const int cp1 = min(m + 1, ARv - 1);

    // 6 taps, each: LDS.128 (ch0-3) + LDS (ch4)
    const float* p0a = sa + (r0*ARv + cm1)*CPAD;
    const float* p0b = sa + (r0*ARv + m  )*CPAD;
    const float* p0c = sa + (r0*ARv + cp1)*CPAD;
    const float* p1a = sa + (r1*ARv + cm1)*CPAD;
    const float* p1b = sa + (r1*ARv + m  )*CPAD;
    const float* p1c = sa + (r1*ARv + cp1)*CPAD;
    float4 v0a = *(const float4*)p0a; float w0a = p0a[4];
    float4 v0b = *(const float4*)p0b; float w0b = p0b[4];
    float4 v0c = *(const float4*)p0c; float w0c = p0c[4];
    float4 v1a = *(const float4*)p1a; float w1a = p1a[4];
    float4 v1b = *(const float4*)p1b; float w1b = p1b[4];
    float4 v1c = *(const float4*)p1c; float w1c = p1c[4];

    float l0a[NBv] = {v0a.x, v0a.y, v0a.z, v0a.w, w0a};
    float l0b[NBv] = {v0b.x, v0b.y, v0b.z, v0b.w, w0b};
    float l0c[NBv] = {v0c.x, v0c.y, v0c.z, v0c.w, w0c};
    float l1a[NBv] = {v1a.x, v1a.y, v1a.z, v1a.w, w1a};
    float l1b[NBv] = {v1b.x, v1b.y, v1b.z, v1b.w, w1b};
    float l1c[NBv] = {v1c.x, v1c.y, v1c.z, v1c.w, w1c};

    float a0[NBv], a1[NBv], a2[NBv], a3[NBv];
    #pragma unroll
    for (int c = 0; c < NBv; c++) {
        float u0 = fmaf(wy, l1a[c] - l0a[c], l0a[c]);
        float u1 = fmaf(wy, l1b[c] - l0b[c], l0b[c]);
        float u2 = fmaf(wy, l1c[c] - l0c[c], l0c[c]);
        a0[c] = fmaf(0.375f, u0, 0.625f * u1);
        a1[c] = fmaf(0.125f, u0, 0.875f * u1);
        a2[c] = fmaf(0.125f, u2, 0.875f * u1);
        a3[c] = fmaf(0.375f, u2, 0.625f * u1);
    }

    float4 res;
    {
        float s = 0.f, dt = 0.f;
        #pragma unroll
        for (int c = 0; c < NBv; c++) { float e = ex2(a0[c]); s += e; dt = fmaf(e, pv[c].x, dt); }
        float z = __fdividef(dt, s);
        res.x = fmaf(0.5f, tanh_ap(0.5f * z), 0.5f);
    }
    {
        float s = 0.f, dt = 0.f;
        #pragma unroll
        for (int c = 0; c < NBv; c++) { float e = ex2(a1[c]); s += e; dt = fmaf(e, pv[c].y, dt); }
        float z = __fdividef(dt, s);
        res.y = fmaf(0.5f, tanh_ap(0.5f * z), 0.5f);
    }
    {
        float s = 0.f, dt = 0.f;
        #pragma unroll
        for (int c = 0; c < NBv; c++) { float e = ex2(a2[c]); s += e; dt = fmaf(e, pv[c].z, dt); }
        float z = __fdividef(dt, s);
        res.z = fmaf(0.5f, tanh_ap(0.5f * z), 0.5f);
    }
    {
        float s = 0.f, dt = 0.f;
        #pragma unroll
        for (int c = 0; c < NBv; c++) { float e = ex2(a3[c]); s += e; dt = fmaf(e, pv[c].w, dt); }
        float z = __fdividef(dt, s);
        res.w = fmaf(0.5f, tanh_ap(0.5f * z), 0.5f);
    }
    return res;
}

__global__ __launch_bounds__(256, 4) void mask2_fused_kernel(
    const float* __restrict__ attn,
    const int*   __restrict__ num_det,
    const float* __restrict__ det_boxes,
    const float* __restrict__ det_scores,
    const int*   __restrict__ det_classes,
    const int*   __restrict__ det_indices,
    const float* __restrict__ pooled,
    float*       __restrict__ out)
{
    const int blk = blockIdx.x;
    if (blk == 2 * Bv * MAXD) {
        int t = threadIdx.x;
        if (t < Bv) out[t] = (float)num_det[t];
        const float4* bx4 = (const float4*)det_boxes;
        float4* ob4 = (float4*)(out + OFF_BOX);
        for (int i = t; i < Bv*MAXD; i += blockDim.x) ob4[i] = bx4[i];
        const float4* sc4 = (const float4*)det_scores;
        float4* os4 = (float4*)(out + OFF_SCR);
        for (int i = t; i < Bv*MAXD/4; i += blockDim.x) os4[i] = sc4[i];
        for (int i = t; i < Bv*MAXD; i += blockDim.x) out[OFF_CLS + i] = (float)det_classes[i];
        return;
    }

    const int d = blk >> 1;            // detection 0..399
    const int h = blk & 1;             // half: output rows [28h, 28h+28)
    const int b = d / MAXD;
    const int tid = threadIdx.x;

    const float4* pb4 = (const float4*)(pooled + (size_t)d * NBv * PIX);
    float4* op4 = (float4*)(out + OFF_MSK + (size_t)d * PIX);

    const int j0 = h * HALF + tid;            // always valid
    const int j1 = j0 + 256;                  // valid for tid < 136
    const bool has1 = tid < (HALF - 256);

    // ---- Prefetch pooled planes for item 0 BEFORE the barrier ----
    float4 pv0[NBv];
    #pragma unroll
    for (int c = 0; c < NBv; c++) pv0[c] = pb4[c * V4PD + j0];

    // ---- Gather 8 src rows/channel into transposed smem, scaled by log2e ----
    // half 0 -> src rows 0..7, half 1 -> src rows 6..13
    __shared__ float sa[8 * ARv * CPAD];      // 896 floats
    {
        const int idx = __ldg(det_indices + d);
        const float4* ap4 = (const float4*)(attn + ((size_t)b * Nv + (size_t)idx) * ATT);
        if (tid < NBv * 28) {                 // 8*14/4 = 28 float4 per channel
            const int ch = tid / 28;
            const int k  = tid - ch * 28;
            float4 v = ap4[ch * (ARv*ARv/4) + h * (6*ARv/4) + k];
            const int f = k * 4;              // float offset within 8x14 window
            const float vv[4] = {v.x, v.y, v.z, v.w};
            #pragma unroll
            for (int e = 0; e < 4; e++) {
                const int ff = f + e;
                const int r  = ff / ARv;
                const int cc = ff - r * ARv;
                sa[(r*ARv + cc)*CPAD + ch] = vv[e] * 1.4426950408889634f;
            }
        }
    }
    __syncthreads();

    // Issue item-1 pooled loads now; latency hides under item-0 compute.
    float4 pv1[NBv];
    if (has1) {
        #pragma unroll
        for (int c = 0; c < NBv; c++) pv1[c] = pb4[c * V4PD + j1];
    }

    const int rowoff = 6 * h;
    op4[j0] = compute_item(j0, rowoff, sa, pv0);
    if (has1) op4[j1] = compute_item(j1, rowoff, sa, pv1);
}

extern "C" void kernel_launch(void* const* d_in, const int* in_sizes, int n_in,
                              void* d_out, int out_size) {
    const float* attn        = (const float*)d_in[1];
    const int*   num_det     = (const int*)  d_in[3];
    const float* det_boxes   = (const float*)d_in[4];
    const float* det_scores  = (const float*)d_in[5];
    const int*   det_classes = (const int*)  d_in[6];
    const int*   det_indices = (const int*)  d_in[7];
    const float* pooled      = (const float*)d_in[8];
    float* out = (float*)d_out;

    mask2_fused_kernel<<<2 * Bv * MAXD + 1, 256>>>(
        attn, num_det, det_boxes, det_scores, det_classes,
        det_indices, pooled, out);
}

// round 6
// speedup vs baseline: 1.5364x; 1.5364x over previous
#include <cuda_runtime.h>
#include <cuda_bf16.h>

#define Bv   4
#define Nv   25200
#define MAXD 100
#define NBv  5
#define ARv  14
#define MRv  56
#define ATT  (NBv*ARv*ARv)     // 980
#define PIX  (MRv*MRv)         // 3136
#define V4PD (PIX/4)           // 784 float4 per detection
#define HALF (V4PD/2)          // 392 float4 per half
#define SROWS 8                // src rows gathered per half
#define SCH  (SROWS*ARv)       // 112 floats per channel in smem
#define L2E  1.4426950408889634f

#define OFF_BOX   4
#define OFF_SCR   (4 + Bv*MAXD*4)
#define OFF_CLS   (OFF_SCR + Bv*MAXD)
#define OFF_MSK   (OFF_CLS + Bv*MAXD)

__device__ __forceinline__ float ex2(float x) {
    float r; asm("ex2.approx.f32 %0, %1;" : "=f"(r) : "f"(x)); return r;
}
__device__ __forceinline__ float tanh_ap(float x) {
    float r; asm("tanh.approx.f32 %0, %1;" : "=f"(r) : "f"(x)); return r;
}

// Channel-major smem (conflict-free scalar LDS), values pre-scaled by log2(e).
// sa[c*SCH + r*14 + col], r is row within the 8-row window (offset rowoff).
__device__ __forceinline__ float4 compute_item(int j, int rowoff,
                                               const float* __restrict__ sa,
                                               const float4* __restrict__ pv)
{
    const int y = j / (MRv/4);            // output row 0..55
    const int m = j - y * (MRv/4);        // float4 col group 0..13

    const float cy = y * 0.25f - 0.375f;
    const float fy = floorf(cy);
    const float wy = cy - fy;
    const int iy = (int)fy;
    const int r0 = max(0, min(ARv - 1, iy))     - rowoff;  // 0..7
    const int r1 = max(0, min(ARv - 1, iy + 1)) - rowoff;

    const int cm1 = max(m - 1, 0);
    const int cp1 = min(m + 1, ARv - 1);

    float a0[NBv], a1[NBv], a2[NBv], a3[NBv];
    #pragma unroll
    for (int c = 0; c < NBv; c++) {
        const float* s0 = sa + c * SCH + r0 * ARv;
        const float* s1 = sa + c * SCH + r1 * ARv;
        float u0 = fmaf(wy, s1[cm1] - s0[cm1], s0[cm1]);
        float u1 = fmaf(wy, s1[m]   - s0[m],   s0[m]);
        float u2 = fmaf(wy, s1[cp1] - s0[cp1], s0[cp1]);
        const float tlo = 0.625f * u1;
        const float thi = 0.875f * u1;
        a0[c] = fmaf(0.375f, u0, tlo);
        a1[c] = fmaf(0.125f, u0, thi);
        a2[c] = fmaf(0.125f, u2, thi);
        a3[c] = fmaf(0.375f, u2, tlo);
    }

    float4 res;
    {
        float s = 0.f, dt = 0.f;
        #pragma unroll
        for (int c = 0; c < NBv; c++) { float e = ex2(a0[c]); s += e; dt = fmaf(e, pv[c].x, dt); }
        res.x = fmaf(0.5f, tanh_ap(0.5f * __fdividef(dt, s)), 0.5f);
    }
    {
        float s = 0.f, dt = 0.f;
        #pragma unroll
        for (int c = 0; c < NBv; c++) { float e = ex2(a1[c]); s += e; dt = fmaf(e, pv[c].y, dt); }
        res.y = fmaf(0.5f, tanh_ap(0.5f * __fdividef(dt, s)), 0.5f);
    }
    {
        float s = 0.f, dt = 0.f;
        #pragma unroll
        for (int c = 0; c < NBv; c++) { float e = ex2(a2[c]); s += e; dt = fmaf(e, pv[c].z, dt); }
        res.z = fmaf(0.5f, tanh_ap(0.5f * __fdividef(dt, s)), 0.5f);
    }
    {
        float s = 0.f, dt = 0.f;
        #pragma unroll
        for (int c = 0; c < NBv; c++) { float e = ex2(a3[c]); s += e; dt = fmaf(e, pv[c].w, dt); }
        res.w = fmaf(0.5f, tanh_ap(0.5f * __fdividef(dt, s)), 0.5f);
    }
    return res;
}

__global__ __launch_bounds__(256, 4) void mask2_fused_kernel(
    const float* __restrict__ attn,
    const int*   __restrict__ num_det,
    const float* __restrict__ det_boxes,
    const float* __restrict__ det_scores,
    const int*   __restrict__ det_classes,
    const int*   __restrict__ det_indices,
    const float* __restrict__ pooled,
    float*       __restrict__ out)
{
    const int blk = blockIdx.x;
    if (blk == 2 * Bv * MAXD) {
        int t = threadIdx.x;
        if (t < Bv) out[t] = (float)num_det[t];
        const float4* bx4 = (const float4*)det_boxes;
        float4* ob4 = (float4*)(out + OFF_BOX);
        for (int i = t; i < Bv*MAXD; i += blockDim.x) ob4[i] = bx4[i];
        const float4* sc4 = (const float4*)det_scores;
        float4* os4 = (float4*)(out + OFF_SCR);
        for (int i = t; i < Bv*MAXD/4; i += blockDim.x) os4[i] = sc4[i];
        for (int i = t; i < Bv*MAXD; i += blockDim.x) out[OFF_CLS + i] = (float)det_classes[i];
        return;
    }

    const int d = blk >> 1;            // detection 0..399
    const int h = blk & 1;             // half: output rows [28h, 28h+28)
    const int b = d / MAXD;
    const int tid = threadIdx.x;

    const float4* pb4 = (const float4*)(pooled + (size_t)d * NBv * PIX);
    float4* op4 = (float4*)(out + OFF_MSK + (size_t)d * PIX);

    const int j0 = h * HALF + tid;            // always valid
    const int j1 = j0 + 256;                  // valid for tid < 136
    const bool has1 = tid < (HALF - 256);

    // ---- Prefetch pooled planes for item 0 BEFORE the barrier ----
    float4 pv0[NBv];
    #pragma unroll
    for (int c = 0; c < NBv; c++) pv0[c] = pb4[c * V4PD + j0];

    // ---- Gather 8 src rows/channel (560 floats), scaled by log2(e) ----
    // half 0 -> src rows 0..7, half 1 -> src rows 6..13
    __shared__ float sa[NBv * SCH];
    {
        const int idx = __ldg(det_indices + d);
        const float4* ap4 = (const float4*)(attn + ((size_t)b * Nv + (size_t)idx) * ATT);
        if (tid < NBv * SCH / 4) {            // 140 float4
            const int ch = tid / (SCH/4);     // /28
            const int rf = tid - ch * (SCH/4);
            float4 v = ap4[ch * (ARv*ARv/4) + h * (6*ARv/4) + rf];
            v.x *= L2E; v.y *= L2E; v.z *= L2E; v.w *= L2E;
            ((float4*)sa)[ch * (SCH/4) + rf] = v;
        }
    }
    __syncthreads();

    const int rowoff = 6 * h;
    op4[j0] = compute_item(j0, rowoff, sa, pv0);

    // Item 1: load pooled after item-0 store (low reg pressure; latency
    // covered by the other resident warps).
    if (has1) {
        float4 pv1[NBv];
        #pragma unroll
        for (int c = 0; c < NBv; c++) pv1[c] = pb4[c * V4PD + j1];
        op4[j1] = compute_item(j1, rowoff, sa, pv1);
    }
}

extern "C" void kernel_launch(void* const* d_in, const int* in_sizes, int n_in,
                              void* d_out, int out_size) {
    const float* attn        = (const float*)d_in[1];
    const int*   num_det     = (const int*)  d_in[3];
    const float* det_boxes   = (const float*)d_in[4];
    const float* det_scores  = (const float*)d_in[5];
    const int*   det_classes = (const int*)  d_in[6];
    const int*   det_indices = (const int*)  d_in[7];
    const float* pooled      = (const float*)d_in[8];
    float* out = (float*)d_out;

    mask2_fused_kernel<<<2 * Bv * MAXD + 1, 256>>>(
        attn, num_det, det_boxes, det_scores, det_classes,
        det_indices, pooled, out);
}

// round 7
// speedup vs baseline: 1.9446x; 1.2657x over previous
#include <cuda_runtime.h>
#include <cuda_bf16.h>

#define Bv   4
#define Nv   25200
#define MAXD 100
#define NBv  5
#define ARv  14
#define MRv  56
#define ATT  (NBv*ARv*ARv)     // 980
#define PIX  (MRv*MRv)         // 3136
#define V4PD (PIX/4)           // 784 float4 per detection
#define NITEMS (Bv*MAXD*V4PD)  // 313600 total float4 items
#define L2E  1.4426950408889634f

#define OFF_BOX   4
#define OFF_SCR   (4 + Bv*MAXD*4)
#define OFF_CLS   (OFF_SCR + Bv*MAXD)
#define OFF_MSK   (OFF_CLS + Bv*MAXD)

__device__ __forceinline__ float ex2(float x) {
    float r; asm("ex2.approx.f32 %0, %1;" : "=f"(r) : "f"(x)); return r;
}
__device__ __forceinline__ float tanh_ap(float x) {
    float r; asm("tanh.approx.f32 %0, %1;" : "=f"(r) : "f"(x)); return r;
}

__global__ __launch_bounds__(256, 5) void mask2_fused_kernel(
    const float* __restrict__ attn,
    const int*   __restrict__ num_det,
    const float* __restrict__ det_boxes,
    const float* __restrict__ det_scores,
    const int*   __restrict__ det_classes,
    const int*   __restrict__ det_indices,
    const float* __restrict__ pooled,
    float*       __restrict__ out)
{
    const int blk = blockIdx.x;
    if (blk == NITEMS / 256) {
        int t = threadIdx.x;
        if (t < Bv) out[t] = (float)num_det[t];
        const float4* bx4 = (const float4*)det_boxes;
        float4* ob4 = (float4*)(out + OFF_BOX);
        for (int i = t; i < Bv*MAXD; i += blockDim.x) ob4[i] = bx4[i];
        const float4* sc4 = (const float4*)det_scores;
        float4* os4 = (float4*)(out + OFF_SCR);
        for (int i = t; i < Bv*MAXD/4; i += blockDim.x) os4[i] = sc4[i];
        for (int i = t; i < Bv*MAXD; i += blockDim.x) out[OFF_CLS + i] = (float)det_classes[i];
        return;
    }

    const int t  = blk * 256 + threadIdx.x;   // 0..313599
    const int d  = t / V4PD;                  // detection 0..399
    const int j  = t - d * V4PD;              // item within detection 0..783
    const int b  = d / MAXD;

    // ---- pooled planes for this item: 5 coalesced LDG.128, issued first ----
    const float4* pb4 = (const float4*)pooled + (size_t)d * NBv * V4PD + j;
    float4 pv0 = __ldg(pb4);
    float4 pv1 = __ldg(pb4 + V4PD);
    float4 pv2 = __ldg(pb4 + 2*V4PD);
    float4 pv3 = __ldg(pb4 + 3*V4PD);
    float4 pv4 = __ldg(pb4 + 4*V4PD);

    // ---- geometry (bilinear 14->56, half-pixel centers, edge clamp) ----
    const int y = j / (MRv/4);                // output row 0..55
    const int m = j - y * (MRv/4);            // float4 col group 0..13

    const float cy = y * 0.25f - 0.375f;
    const float fy = floorf(cy);
    const float wy = cy - fy;
    const int iy = (int)fy;
    const int r0 = max(0, min(ARv - 1, iy));
    const int r1 = max(0, min(ARv - 1, iy + 1));

    const int cm1 = max(m - 1, 0);
    const int cp1 = min(m + 1, ARv - 1);

    // attn row for this detection (L1-broadcast across the ~784 threads of d)
    const int idx = __ldg(det_indices + d);
    const float* ar = attn + ((size_t)b * Nv + (size_t)idx) * ATT;

    // horizontal weights with log2(e) folded in (bilinear is linear)
    const float WL0 = 0.375f * L2E, WL1 = 0.625f * L2E;
    const float WH0 = 0.125f * L2E, WH1 = 0.875f * L2E;

    float s0 = 0.f, s1 = 0.f, s2 = 0.f, s3 = 0.f;
    float d0 = 0.f, d1 = 0.f, d2 = 0.f, d3 = 0.f;

    #pragma unroll
    for (int c = 0; c < NBv; c++) {
        const float* rc = ar + c * (ARv*ARv);
        const float* q0 = rc + r0 * ARv;
        const float* q1 = rc + r1 * ARv;
        float t0a = __ldg(q0 + cm1), t0b = __ldg(q0 + m), t0c = __ldg(q0 + cp1);
        float t1a = __ldg(q1 + cm1), t1b = __ldg(q1 + m), t1c = __ldg(q1 + cp1);

        float u0 = fmaf(wy, t1a - t0a, t0a);
        float u1 = fmaf(wy, t1b - t0b, t0b);
        float u2 = fmaf(wy, t1c - t0c, t0c);

        float tlo = WL1 * u1;
        float thi = WH1 * u1;
        float e0 = ex2(fmaf(WL0, u0, tlo));
        float e1 = ex2(fmaf(WH0, u0, thi));
        float e2 = ex2(fmaf(WH0, u2, thi));
        float e3 = ex2(fmaf(WL0, u2, tlo));

        float4 pv = (c == 0) ? pv0 : (c == 1) ? pv1 : (c == 2) ? pv2 : (c == 3) ? pv3 : pv4;
        s0 += e0; d0 = fmaf(e0, pv.x, d0);
        s1 += e1; d1 = fmaf(e1, pv.y, d1);
        s2 += e2; d2 = fmaf(e2, pv.z, d2);
        s3 += e3; d3 = fmaf(e3, pv.w, d3);
    }

    float4 res;
    res.x = fmaf(0.5f, tanh_ap(0.5f * __fdividef(d0, s0)), 0.5f);
    res.y = fmaf(0.5f, tanh_ap(0.5f * __fdividef(d1, s1)), 0.5f);
    res.z = fmaf(0.5f, tanh_ap(0.5f * __fdividef(d2, s2)), 0.5f);
    res.w = fmaf(0.5f, tanh_ap(0.5f * __fdividef(d3, s3)), 0.5f);

    ((float4*)(out + OFF_MSK))[t] = res;
}

extern "C" void kernel_launch(void* const* d_in, const int* in_sizes, int n_in,
                              void* d_out, int out_size) {
    const float* attn        = (const float*)d_in[1];
    const int*   num_det     = (const int*)  d_in[3];
    const float* det_boxes   = (const float*)d_in[4];
    const float* det_scores  = (const float*)d_in[5];
    const int*   det_classes = (const int*)  d_in[6];
    const int*   det_indices = (const int*)  d_in[7];
    const float* pooled      = (const float*)d_in[8];
    float* out = (float*)d_out;

    mask2_fused_kernel<<<NITEMS / 256 + 1, 256>>>(
        attn, num_det, det_boxes, det_scores, det_classes,
        det_indices, pooled, out);
}